// round 15
// baseline (speedup 1.0000x reference)
#include <cuda_runtime.h>
#include <cuda_bf16.h>
#include <cstdint>

#define NMAX 50000
#define EMAX 800000
#define D 128
#define EF_TILE 256   // edges per pipeline stage in k_edgefeat

// ---------------- f32x2 packed helpers ----------------
#define FMA2(d, a, b) \
    asm("fma.rn.f32x2 %0, %1, %2, %0;" : "+l"(d) : "l"(a), "l"(b))

__device__ __forceinline__ unsigned long long pk(float lo, float hi) {
    unsigned long long r;
    asm("mov.b64 %0, {%1, %2};" : "=l"(r) : "f"(lo), "f"(hi));
    return r;
}
__device__ __forceinline__ float2 upk(unsigned long long v) {
    float lo, hi;
    asm("mov.b64 {%0, %1}, %2;" : "=f"(lo), "=f"(hi) : "l"(v));
    return make_float2(lo, hi);
}

// cp.async helpers
__device__ __forceinline__ void cp16(uint32_t saddr, const void* g) {
    asm volatile("cp.async.ca.shared.global [%0], [%1], 16;" :: "r"(saddr), "l"(g));
}
__device__ __forceinline__ void cp4(uint32_t saddr, const void* g) {
    asm volatile("cp.async.ca.shared.global [%0], [%1], 4;" :: "r"(saddr), "l"(g));
}
#define CP_COMMIT()  asm volatile("cp.async.commit_group;" ::: "memory")
#define CP_WAIT(N)   asm volatile("cp.async.wait_group %0;" :: "n"(N) : "memory")

// ---------------- device scratch ----------------
__device__ float g_xn[NMAX * D];        // layernormed x
__device__ float g_xw1[NMAX * 32];      // action layer1 projections, pre-scaled by dinv1
__device__ float g_acc1[NMAX * 32];     // scatter accumulator layer1
__device__ float g_t2[NMAX * 4];        // layer2 projections pre-scaled by dinv1
__device__ float g_acc2[NMAX * 4];      // scatter accumulator layer2
__device__ float g_dinv1[NMAX];
__device__ int   g_deg1[NMAX];
__device__ int   g_degm[NMAX];
__device__ float g_dinvm[NMAX];
__device__ unsigned char g_flags[NMAX]; // bit0 = in0, bit1 = out0
__device__ float g_xws[NMAX * D];       // (xn @ conv_w) * dinvm
__device__ int2  g_act[EMAX];           // compacted active edges (src,dst)
__device__ int   g_nact;

// vector reduction into global (sm_90+)
__device__ __forceinline__ void red4(float* p, float4 v) {
    asm volatile("red.global.add.v4.f32 [%0], {%1,%2,%3,%4};"
                 :: "l"(p), "f"(v.x), "f"(v.y), "f"(v.z), "f"(v.w) : "memory");
}

// ---------------- kernels ----------------

// Vectorized zero of out (n*32 float4), acc1 (n*8 float4), acc2, degrees.
__global__ void k_init(float* __restrict__ out, int n) {
    int i = blockIdx.x * blockDim.x + threadIdx.x;
    float4 z = make_float4(0.f, 0.f, 0.f, 0.f);
    if (i < n * 32) ((float4*)out)[i] = z;       // out: n*128 floats
    if (i < n * 8)  ((float4*)g_acc1)[i] = z;    // acc1: n*32 floats
    if (i < n) {
        ((float4*)g_acc2)[i] = z;                // acc2: n*4 floats
        g_deg1[i] = 0;
        g_degm[i] = 0;
    }
    if (i == 0) g_nact = 0;
}

__global__ void k_deg1(const int* __restrict__ ei, int e_cnt) {
    int e = blockIdx.x * blockDim.x + threadIdx.x;
    if (e >= e_cnt) return;
    atomicAdd(&g_deg1[ei[e_cnt + e]], 1);
}

// LayerNorm + both action-net layer-1 projections (fused), f32x2 inner product.
__global__ __launch_bounds__(256) void k_ln_proj(
    const float* __restrict__ x, const float* __restrict__ ln_g, const float* __restrict__ ln_b,
    const float* __restrict__ ia1_w, const float* __restrict__ oa1_w, int n)
{
    __shared__ unsigned long long sWp[64 * 32];  // k-pairs: (W[2p][j], W[2p+1][j])
    __shared__ float sxn[8][D];
    int tid = threadIdx.x;
    for (int i = tid; i < 64 * 32; i += 256) {
        int p = i >> 5, j = i & 31;
        float w0 = (j < 16) ? ia1_w[(2 * p) * 16 + j]     : oa1_w[(2 * p) * 16 + (j - 16)];
        float w1 = (j < 16) ? ia1_w[(2 * p + 1) * 16 + j] : oa1_w[(2 * p + 1) * 16 + (j - 16)];
        sWp[i] = pk(w0, w1);
    }
    __syncthreads();
    int warp = tid >> 5, lane = tid & 31;
    int nwarps = gridDim.x * 8;
    for (int v = blockIdx.x * 8 + warp; v < n; v += nwarps) {
        float4 xv = ((const float4*)(x + (size_t)v * D))[lane];
        float s1 = xv.x + xv.y + xv.z + xv.w;
        float s2 = xv.x * xv.x + xv.y * xv.y + xv.z * xv.z + xv.w * xv.w;
        #pragma unroll
        for (int o = 16; o; o >>= 1) {
            s1 += __shfl_xor_sync(0xffffffffu, s1, o);
            s2 += __shfl_xor_sync(0xffffffffu, s2, o);
        }
        float mu = s1 * (1.f / 128.f);
        float var = s2 * (1.f / 128.f) - mu * mu;
        float rs = rsqrtf(var + 1e-5f);
        float4 g4 = ((const float4*)ln_g)[lane];
        float4 b4 = ((const float4*)ln_b)[lane];
        float4 o4;
        o4.x = (xv.x - mu) * rs * g4.x + b4.x;
        o4.y = (xv.y - mu) * rs * g4.y + b4.y;
        o4.z = (xv.z - mu) * rs * g4.z + b4.z;
        o4.w = (xv.w - mu) * rs * g4.w + b4.w;
        ((float4*)(g_xn + (size_t)v * D))[lane] = o4;
        ((float4*)sxn[warp])[lane] = o4;
        __syncwarp();
        float dinv = rsqrtf((float)g_deg1[v] + 1.0f);
        unsigned long long acc2 = 0ull;
        const float* sx = sxn[warp];
        #pragma unroll 16
        for (int p = 0; p < 64; p++) {
            unsigned long long xp = *(const unsigned long long*)(sx + 2 * p);
            FMA2(acc2, xp, sWp[p * 32 + lane]);
        }
        float2 u = upk(acc2);
        g_xw1[v * 32 + lane] = (u.x + u.y) * dinv;
        if (lane == 0) g_dinv1[v] = dinv;
        __syncwarp();
    }
}

// edge_features = relu(edge_attr @ ep_w + ep_b), scattered into zeroed out.
// cp.async double-buffered tile pipeline + intra-tile register prefetch.
// Persistent grid: 2 CTAs/SM (304 blocks). Runs on a forked stream,
// overlapped with the action-net chain.
__global__ __launch_bounds__(256) void k_edgefeat(const int* __restrict__ ei,
                                                  const float* __restrict__ ea,
                                                  const float* __restrict__ ep_w,
                                                  const float* __restrict__ ep_b,
                                                  float* __restrict__ out, int e_cnt)
{
    __shared__ float s_ea[2][EF_TILE * 16];
    __shared__ int   s_dst[2][EF_TILE];

    int tid = threadIdx.x, lane = tid & 31, warp = tid >> 5;
    unsigned long long wkp[8][4];
    #pragma unroll
    for (int p = 0; p < 8; p++) {
        float4 w0 = ((const float4*)(ep_w + (size_t)(2 * p) * D))[lane];
        float4 w1 = ((const float4*)(ep_w + (size_t)(2 * p + 1) * D))[lane];
        wkp[p][0] = pk(w0.x, w1.x);
        wkp[p][1] = pk(w0.y, w1.y);
        wkp[p][2] = pk(w0.z, w1.z);
        wkp[p][3] = pk(w0.w, w1.w);
    }
    float4 bb = ((const float4*)ep_b)[lane];

    uint32_t sa0 = (uint32_t)__cvta_generic_to_shared(&s_ea[0][0]);
    uint32_t sa1 = (uint32_t)__cvta_generic_to_shared(&s_ea[1][0]);
    uint32_t sd0 = (uint32_t)__cvta_generic_to_shared(&s_dst[0][0]);
    uint32_t sd1 = (uint32_t)__cvta_generic_to_shared(&s_dst[1][0]);

    int ntiles = (e_cnt + EF_TILE - 1) / EF_TILE;
    int t = blockIdx.x;
    int stride = gridDim.x;

    // stage tile t into buf 0
    if (t < ntiles) {
        int base = t * EF_TILE;
        #pragma unroll
        for (int c = tid; c < EF_TILE * 4; c += 256) {
            int eg = base + (c >> 2);
            if (eg < e_cnt) cp16(sa0 + c * 16, ea + (size_t)eg * 16 + (c & 3) * 4);
        }
        #pragma unroll
        for (int c = tid; c < EF_TILE; c += 256) {
            int eg = base + c;
            if (eg < e_cnt) cp4(sd0 + c * 4, ei + e_cnt + eg);
        }
    }
    CP_COMMIT();

    int buf = 0;
    for (; t < ntiles; t += stride) {
        int nxt = t + stride;
        if (nxt < ntiles) {            // stage next tile into other buffer
            int base = nxt * EF_TILE;
            uint32_t sa = buf ? sa0 : sa1;
            uint32_t sd = buf ? sd0 : sd1;
            #pragma unroll
            for (int c = tid; c < EF_TILE * 4; c += 256) {
                int eg = base + (c >> 2);
                if (eg < e_cnt) cp16(sa + c * 16, ea + (size_t)eg * 16 + (c & 3) * 4);
            }
            #pragma unroll
            for (int c = tid; c < EF_TILE; c += 256) {
                int eg = base + c;
                if (eg < e_cnt) cp4(sd + c * 4, ei + e_cnt + eg);
            }
            CP_COMMIT();
            CP_WAIT(1);                // current tile's group done
        } else {
            CP_COMMIT();
            CP_WAIT(1);
        }
        __syncthreads();

        // compute current tile from smem: warp w handles EF_TILE/8 edges
        int base = t * EF_TILE;
        const float* sea = s_ea[buf];
        const int*   sds = s_dst[buf];
        int per = EF_TILE / 8;
        int j0 = warp * per;
        int jend = min(j0 + per, e_cnt - base);
        if (j0 < jend) {
            // preload first edge
            const ulonglong2* row = (const ulonglong2*)(sea + j0 * 16);
            ulonglong2 q0 = row[0], q1 = row[1], q2 = row[2], q3 = row[3];
            int dnx = sds[j0];
            for (int j = j0; j < jend; j++) {
                ulonglong2 c0 = q0, c1 = q1, c2 = q2, c3 = q3;
                int d = dnx;
                if (j + 1 < jend) {    // prefetch next edge BEFORE red4 clobber
                    const ulonglong2* r2 = (const ulonglong2*)(sea + (j + 1) * 16);
                    q0 = r2[0]; q1 = r2[1]; q2 = r2[2]; q3 = r2[3];
                    dnx = sds[j + 1];
                }
                unsigned long long t0 = 0ull, t1 = 0ull, t2 = 0ull, t3 = 0ull;
                FMA2(t0, c0.x, wkp[0][0]); FMA2(t1, c0.x, wkp[0][1]); FMA2(t2, c0.x, wkp[0][2]); FMA2(t3, c0.x, wkp[0][3]);
                FMA2(t0, c0.y, wkp[1][0]); FMA2(t1, c0.y, wkp[1][1]); FMA2(t2, c0.y, wkp[1][2]); FMA2(t3, c0.y, wkp[1][3]);
                FMA2(t0, c1.x, wkp[2][0]); FMA2(t1, c1.x, wkp[2][1]); FMA2(t2, c1.x, wkp[2][2]); FMA2(t3, c1.x, wkp[2][3]);
                FMA2(t0, c1.y, wkp[3][0]); FMA2(t1, c1.y, wkp[3][1]); FMA2(t2, c1.y, wkp[3][2]); FMA2(t3, c1.y, wkp[3][3]);
                FMA2(t0, c2.x, wkp[4][0]); FMA2(t1, c2.x, wkp[4][1]); FMA2(t2, c2.x, wkp[4][2]); FMA2(t3, c2.x, wkp[4][3]);
                FMA2(t0, c2.y, wkp[5][0]); FMA2(t1, c2.y, wkp[5][1]); FMA2(t2, c2.y, wkp[5][2]); FMA2(t3, c2.y, wkp[5][3]);
                FMA2(t0, c3.x, wkp[6][0]); FMA2(t1, c3.x, wkp[6][1]); FMA2(t2, c3.x, wkp[6][2]); FMA2(t3, c3.x, wkp[6][3]);
                FMA2(t0, c3.y, wkp[7][0]); FMA2(t1, c3.y, wkp[7][1]); FMA2(t2, c3.y, wkp[7][2]); FMA2(t3, c3.y, wkp[7][3]);
                float2 u0 = upk(t0), u1 = upk(t1), u2 = upk(t2), u3 = upk(t3);
                float4 r;
                r.x = fmaxf(bb.x + u0.x + u0.y, 0.f);
                r.y = fmaxf(bb.y + u1.x + u1.y, 0.f);
                r.z = fmaxf(bb.z + u2.x + u2.y, 0.f);
                r.w = fmaxf(bb.w + u3.x + u3.y, 0.f);
                red4(out + (size_t)d * D + lane * 4, r);
            }
        }
        __syncthreads();               // buffer free before next stage cycle
        buf ^= 1;
    }
}

// scatter layer-1 messages: one thread per edge, 8 independent red4 (MLP 8).
__global__ void k_scatter1(const int* __restrict__ ei, int e_cnt) {
    int e = blockIdx.x * blockDim.x + threadIdx.x;
    if (e >= e_cnt) return;
    int s = ei[e], d = ei[e_cnt + e];
    const float4* src = (const float4*)(g_xw1 + (size_t)s * 32);
    float* dst = g_acc1 + (size_t)d * 32;
    float4 v0 = src[0], v1 = src[1], v2 = src[2], v3 = src[3];
    float4 v4 = src[4], v5 = src[5], v6 = src[6], v7 = src[7];
    red4(dst + 0,  v0); red4(dst + 4,  v1); red4(dst + 8,  v2); red4(dst + 12, v3);
    red4(dst + 16, v4); red4(dst + 20, v5); red4(dst + 24, v6); red4(dst + 28, v7);
}

// finalize h (relu) + project to layer2 logits contribution (pre-scaled by dinv1)
__global__ void k_fin1(const float* __restrict__ ia1_b, const float* __restrict__ oa1_b,
                       const float* __restrict__ ia2_w, const float* __restrict__ oa2_w, int n)
{
    int tid = blockIdx.x * blockDim.x + threadIdx.x;
    int v = tid >> 5, lane = tid & 31;
    if (v >= n) return;
    float dinv = g_dinv1[v];
    float xw1s = g_xw1[v * 32 + lane];
    float bias = (lane < 16) ? ia1_b[lane] : oa1_b[lane - 16];
    float h = dinv * g_acc1[v * 32 + lane] + xw1s * dinv + bias;
    h = fmaxf(h, 0.f);
    float w0 = (lane < 16) ? ia2_w[lane * 2] : oa2_w[(lane - 16) * 2];
    float w1 = (lane < 16) ? ia2_w[lane * 2 + 1] : oa2_w[(lane - 16) * 2 + 1];
    float p0 = h * w0, p1 = h * w1;
    #pragma unroll
    for (int o = 8; o; o >>= 1) {
        p0 += __shfl_xor_sync(0xffffffffu, p0, o);
        p1 += __shfl_xor_sync(0xffffffffu, p1, o);
    }
    if (lane == 0)  { g_t2[v * 4 + 0] = p0 * dinv; g_t2[v * 4 + 1] = p1 * dinv; }
    if (lane == 16) { g_t2[v * 4 + 2] = p0 * dinv; g_t2[v * 4 + 3] = p1 * dinv; }
}

__global__ void k_scatter2(const int* __restrict__ ei, int e_cnt) {
    int e = blockIdx.x * blockDim.x + threadIdx.x;
    if (e >= e_cnt) return;
    int s = ei[e], d = ei[e_cnt + e];
    float4 t = *(const float4*)(g_t2 + (size_t)s * 4);
    red4(g_acc2 + (size_t)d * 4, t);
}

__global__ void k_gumbel(const float* __restrict__ u_in, const float* __restrict__ u_out,
                         const float* __restrict__ ia2_b, const float* __restrict__ oa2_b, int n)
{
    int v = blockIdx.x * blockDim.x + threadIdx.x;
    if (v >= n) return;
    float dinv = g_dinv1[v];
    float li0 = dinv * g_acc2[v * 4 + 0] + g_t2[v * 4 + 0] * dinv + ia2_b[0];
    float li1 = dinv * g_acc2[v * 4 + 1] + g_t2[v * 4 + 1] * dinv + ia2_b[1];
    float lo0 = dinv * g_acc2[v * 4 + 2] + g_t2[v * 4 + 2] * dinv + oa2_b[0];
    float lo1 = dinv * g_acc2[v * 4 + 3] + g_t2[v * 4 + 3] * dinv + oa2_b[1];
    float gi0 = -logf(-logf(u_in[v * 2 + 0] + 1e-10f) + 1e-10f);
    float gi1 = -logf(-logf(u_in[v * 2 + 1] + 1e-10f) + 1e-10f);
    float go0 = -logf(-logf(u_out[v * 2 + 0] + 1e-10f) + 1e-10f);
    float go1 = -logf(-logf(u_out[v * 2 + 1] + 1e-10f) + 1e-10f);
    int in0  = (li0 + gi0 >= li1 + gi1) ? 1 : 0;
    int out0 = (lo0 + go0 >= lo1 + go1) ? 1 : 0;
    g_flags[v] = (unsigned char)(in0 | (out0 << 1));
}

// weighted degree + warp-aggregated compaction of active edges
__global__ void k_compact(const int* __restrict__ ei, int e_cnt) {
    int e = blockIdx.x * blockDim.x + threadIdx.x;
    int lane = threadIdx.x & 31;
    int s = 0, d = 0, act = 0;
    if (e < e_cnt) {
        s = ei[e]; d = ei[e_cnt + e];
        act = (g_flags[d] & 1) && ((g_flags[s] >> 1) & 1);
    }
    unsigned m = __ballot_sync(0xffffffffu, act);
    if (m) {
        int leader = __ffs(m) - 1;
        int base = 0;
        if (lane == leader) base = atomicAdd(&g_nact, __popc(m));
        base = __shfl_sync(0xffffffffu, base, leader);
        if (act) {
            int r = __popc(m & ((1u << lane) - 1));
            g_act[base + r] = make_int2(s, d);
            atomicAdd(&g_degm[d], 1);
        }
    }
}

// xw = xn @ conv_w (f32x2 packed); dinvm in epilogue; ACCUMULATES into out
// (out already holds edge-feature sums): out += xws*dinvm + conv_b.
__global__ __launch_bounds__(256) void k_gemm(const float* __restrict__ conv_w,
                                              const float* __restrict__ conv_b,
                                              float* __restrict__ out, int n)
{
    __shared__ float sA[64][32];
    __shared__ ulonglong2 sB[16 * 2 * 32];
    float* sBf = (float*)sB;
    int tid = threadIdx.x;
    int lane = tid & 31, warp = tid >> 5;
    int row0 = blockIdx.x * 64, rb = warp * 8;
    unsigned long long acc[8][4];
    #pragma unroll
    for (int r = 0; r < 8; r++)
        #pragma unroll
        for (int c = 0; c < 4; c++) acc[r][c] = 0ull;

    for (int kc = 0; kc < D; kc += 32) {
        for (int i = tid; i < 1024; i += 256) {
            int kk = i >> 5, c = i & 31;
            float4 w = ((const float4*)(conv_w + (size_t)(kc + kk) * D))[c];
            int p = kk >> 1, par = kk & 1;
            int b0i = (((p * 2 + 0) * 32 + c) << 2);
            int b1i = (((p * 2 + 1) * 32 + c) << 2);
            sBf[b0i + par]     = w.x;
            sBf[b0i + 2 + par] = w.y;
            sBf[b1i + par]     = w.z;
            sBf[b1i + 2 + par] = w.w;
        }
        for (int i = tid; i < 512; i += 256) {
            int r = i >> 3, c4 = i & 7;
            float4 vv = make_float4(0.f, 0.f, 0.f, 0.f);
            if (row0 + r < n)
                vv = ((const float4*)(g_xn + (size_t)(row0 + r) * D + kc))[c4];
            sA[r][c4 * 4 + 0] = vv.x; sA[r][c4 * 4 + 1] = vv.y;
            sA[r][c4 * 4 + 2] = vv.z; sA[r][c4 * 4 + 3] = vv.w;
        }
        __syncthreads();
        #pragma unroll
        for (int p = 0; p < 16; p++) {
            ulonglong2 b0 = sB[(p * 2 + 0) * 32 + lane];
            ulonglong2 b1 = sB[(p * 2 + 1) * 32 + lane];
            #pragma unroll
            for (int r = 0; r < 8; r++) {
                unsigned long long ap = *(const unsigned long long*)&sA[rb + r][2 * p];
                FMA2(acc[r][0], ap, b0.x);
                FMA2(acc[r][1], ap, b0.y);
                FMA2(acc[r][2], ap, b1.x);
                FMA2(acc[r][3], ap, b1.y);
            }
        }
        __syncthreads();
    }
    float4 bb = ((const float4*)conv_b)[lane];
    #pragma unroll
    for (int r = 0; r < 8; r++) {
        int v = row0 + rb + r;
        if (v < n) {
            float dm = rsqrtf((float)g_degm[v] + 1.0f);   // fused dinvm
            if (lane == 0) g_dinvm[v] = dm;
            float2 u0 = upk(acc[r][0]), u1 = upk(acc[r][1]);
            float2 u2 = upk(acc[r][2]), u3 = upk(acc[r][3]);
            float4 w = make_float4((u0.x + u0.y) * dm, (u1.x + u1.y) * dm,
                                   (u2.x + u2.y) * dm, (u3.x + u3.y) * dm);
            ((float4*)(g_xws + (size_t)v * D))[lane] = w;
            float4 prev = ((const float4*)(out + (size_t)v * D))[lane];
            float4 o = make_float4(prev.x + w.x * dm + bb.x, prev.y + w.y * dm + bb.y,
                                   prev.z + w.z * dm + bb.z, prev.w + w.w * dm + bb.w);
            ((float4*)(out + (size_t)v * D))[lane] = o;
        }
    }
}

// main conv scatter over compacted active edges; prefetched grid-stride.
__global__ void k_scatter_main(float* __restrict__ out) {
    int gw = (blockIdx.x * blockDim.x + threadIdx.x) >> 5;
    int lane = threadIdx.x & 31;
    int nw = (gridDim.x * blockDim.x) >> 5;
    int nact = g_nact;
    int e = gw;
    int2 sd_nx = make_int2(0, 0);
    if (e < nact) sd_nx = g_act[e];
    while (e < nact) {
        int2 sd = sd_nx;
        int e2 = e + nw;
        if (e2 < nact) sd_nx = g_act[e2];
        float dm = g_dinvm[sd.y];
        float4 v = ((const float4*)(g_xws + (size_t)sd.x * D))[lane];
        v.x *= dm; v.y *= dm; v.z *= dm; v.w *= dm;
        red4(out + (size_t)sd.y * D + lane * 4, v);
        e = e2;
    }
}

__global__ void k_relu(float* __restrict__ out, int n4) {
    int i = blockIdx.x * blockDim.x + threadIdx.x;
    if (i >= n4) return;
    float4 v = ((float4*)out)[i];
    v.x = fmaxf(v.x, 0.f); v.y = fmaxf(v.y, 0.f);
    v.z = fmaxf(v.z, 0.f); v.w = fmaxf(v.w, 0.f);
    ((float4*)out)[i] = v;
}

// ---------------- launch ----------------
extern "C" void kernel_launch(void* const* d_in, const int* in_sizes, int n_in,
                              void* d_out, int out_size)
{
    const float* x      = (const float*)d_in[0];
    const int*   ei     = (const int*)  d_in[1];
    const float* ea     = (const float*)d_in[2];
    const float* u_in   = (const float*)d_in[3];
    const float* u_out  = (const float*)d_in[4];
    const float* ln_g   = (const float*)d_in[5];
    const float* ln_b   = (const float*)d_in[6];
    const float* conv_w = (const float*)d_in[7];
    const float* conv_b = (const float*)d_in[8];
    const float* ep_w   = (const float*)d_in[9];
    const float* ep_b   = (const float*)d_in[10];
    const float* ia1_w  = (const float*)d_in[11];
    const float* ia1_b  = (const float*)d_in[12];
    const float* ia2_w  = (const float*)d_in[13];
    const float* ia2_b  = (const float*)d_in[14];
    const float* oa1_w  = (const float*)d_in[15];
    const float* oa1_b  = (const float*)d_in[16];
    const float* oa2_w  = (const float*)d_in[17];
    const float* oa2_b  = (const float*)d_in[18];

    int n = in_sizes[0] / D;       // 50000
    int e = in_sizes[1] / 2;       // 800000
    float* out = (float*)d_out;

    // Lazy one-time stream/event creation (first call is the uncaptured
    // correctness run; capture reuses the existing handles via the standard
    // event-fork pattern, producing parallel graph branches).
    static cudaStream_t s2 = nullptr;
    static cudaEvent_t evFork = nullptr, evJoin = nullptr;
    if (s2 == nullptr) {
        cudaStreamCreateWithFlags(&s2, cudaStreamNonBlocking);
        cudaEventCreateWithFlags(&evFork, cudaEventDisableTiming);
        cudaEventCreateWithFlags(&evJoin, cudaEventDisableTiming);
    }

    k_init<<<(n * 32 + 255) / 256, 256>>>(out, n);

    // fork: edgefeat on s2, action-net chain on the main stream
    cudaEventRecord(evFork, 0);
    cudaStreamWaitEvent(s2, evFork, 0);
    k_edgefeat<<<304, 256, 0, s2>>>(ei, ea, ep_w, ep_b, out, e);
    cudaEventRecord(evJoin, s2);

    k_deg1<<<(e + 255) / 256, 256>>>(ei, e);
    k_ln_proj<<<592, 256>>>(x, ln_g, ln_b, ia1_w, oa1_w, n);
    k_scatter1<<<(e + 255) / 256, 256>>>(ei, e);
    k_fin1<<<(n * 32 + 255) / 256, 256>>>(ia1_b, oa1_b, ia2_w, oa2_w, n);
    k_scatter2<<<(e + 255) / 256, 256>>>(ei, e);
    k_gumbel<<<(n + 255) / 256, 256>>>(u_in, u_out, ia2_b, oa2_b, n);
    k_compact<<<(e + 255) / 256, 256>>>(ei, e);

    // join: gemm needs out (edgefeat), xn (ln_proj), degm (compact)
    cudaStreamWaitEvent(0, evJoin, 0);
    k_gemm<<<(n + 63) / 64, 256>>>(conv_w, conv_b, out, n);
    k_scatter_main<<<4736, 256>>>(out);
    k_relu<<<(n * 32 + 255) / 256, 256>>>(out, n * 32);
}

// round 16
// speedup vs baseline: 1.0831x; 1.0831x over previous
#include <cuda_runtime.h>
#include <cuda_bf16.h>
#include <cstdint>

#define NMAX 50000
#define EMAX 800000
#define D 128
#define EF_TILE 256   // edges per pipeline stage in k_edgefeat

// ---------------- f32x2 packed helpers ----------------
#define FMA2(d, a, b) \
    asm("fma.rn.f32x2 %0, %1, %2, %0;" : "+l"(d) : "l"(a), "l"(b))

__device__ __forceinline__ unsigned long long pk(float lo, float hi) {
    unsigned long long r;
    asm("mov.b64 %0, {%1, %2};" : "=l"(r) : "f"(lo), "f"(hi));
    return r;
}
__device__ __forceinline__ float2 upk(unsigned long long v) {
    float lo, hi;
    asm("mov.b64 {%0, %1}, %2;" : "=f"(lo), "=f"(hi) : "l"(v));
    return make_float2(lo, hi);
}

// cp.async helpers
__device__ __forceinline__ void cp16(uint32_t saddr, const void* g) {
    asm volatile("cp.async.ca.shared.global [%0], [%1], 16;" :: "r"(saddr), "l"(g));
}
__device__ __forceinline__ void cp4(uint32_t saddr, const void* g) {
    asm volatile("cp.async.ca.shared.global [%0], [%1], 4;" :: "r"(saddr), "l"(g));
}
#define CP_COMMIT()  asm volatile("cp.async.commit_group;" ::: "memory")
#define CP_WAIT(N)   asm volatile("cp.async.wait_group %0;" :: "n"(N) : "memory")

// ---------------- device scratch ----------------
__device__ float g_xn[NMAX * D];        // layernormed x
__device__ float g_xw1[NMAX * 32];      // action layer1 projections, pre-scaled by dinv1
__device__ float g_acc1[NMAX * 32];     // scatter accumulator layer1
__device__ float g_t2[NMAX * 4];        // layer2 projections pre-scaled by dinv1
__device__ float g_acc2[NMAX * 4];      // scatter accumulator layer2
__device__ float g_dinv1[NMAX];
__device__ int   g_deg1[NMAX];
__device__ int   g_degm[NMAX];
__device__ float g_dinvm[NMAX];
__device__ unsigned char g_flags[NMAX]; // bit0 = in0, bit1 = out0
__device__ float g_xws[NMAX * D];       // (xn @ conv_w) * dinvm
__device__ int2  g_act[EMAX];           // compacted active edges (src,dst)
__device__ int   g_nact;

// vector reductions into global (sm_90+)
__device__ __forceinline__ void red4(float* p, float4 v) {
    asm volatile("red.global.add.v4.f32 [%0], {%1,%2,%3,%4};"
                 :: "l"(p), "f"(v.x), "f"(v.y), "f"(v.z), "f"(v.w) : "memory");
}
__device__ __forceinline__ void red2(float* p, float a, float b) {
    asm volatile("red.global.add.v2.f32 [%0], {%1,%2};"
                 :: "l"(p), "f"(a), "f"(b) : "memory");
}

// ---------------- kernels ----------------

// Vectorized zero of out (n*32 float4), acc1 (n*8 float4), acc2, degrees.
__global__ void k_init(float* __restrict__ out, int n) {
    int i = blockIdx.x * blockDim.x + threadIdx.x;
    float4 z = make_float4(0.f, 0.f, 0.f, 0.f);
    if (i < n * 32) ((float4*)out)[i] = z;       // out: n*128 floats
    if (i < n * 8)  ((float4*)g_acc1)[i] = z;    // acc1: n*32 floats
    if (i < n) {
        ((float4*)g_acc2)[i] = z;                // acc2: n*4 floats
        g_deg1[i] = 0;
        g_degm[i] = 0;
    }
    if (i == 0) g_nact = 0;
}

__global__ void k_deg1(const int* __restrict__ ei, int e_cnt) {
    int e = blockIdx.x * blockDim.x + threadIdx.x;
    if (e >= e_cnt) return;
    atomicAdd(&g_deg1[ei[e_cnt + e]], 1);
}

// LayerNorm + both action-net layer-1 projections (fused), f32x2 inner product.
__global__ __launch_bounds__(256) void k_ln_proj(
    const float* __restrict__ x, const float* __restrict__ ln_g, const float* __restrict__ ln_b,
    const float* __restrict__ ia1_w, const float* __restrict__ oa1_w, int n)
{
    __shared__ unsigned long long sWp[64 * 32];  // k-pairs: (W[2p][j], W[2p+1][j])
    __shared__ float sxn[8][D];
    int tid = threadIdx.x;
    for (int i = tid; i < 64 * 32; i += 256) {
        int p = i >> 5, j = i & 31;
        float w0 = (j < 16) ? ia1_w[(2 * p) * 16 + j]     : oa1_w[(2 * p) * 16 + (j - 16)];
        float w1 = (j < 16) ? ia1_w[(2 * p + 1) * 16 + j] : oa1_w[(2 * p + 1) * 16 + (j - 16)];
        sWp[i] = pk(w0, w1);
    }
    __syncthreads();
    int warp = tid >> 5, lane = tid & 31;
    int nwarps = gridDim.x * 8;
    for (int v = blockIdx.x * 8 + warp; v < n; v += nwarps) {
        float4 xv = ((const float4*)(x + (size_t)v * D))[lane];
        float s1 = xv.x + xv.y + xv.z + xv.w;
        float s2 = xv.x * xv.x + xv.y * xv.y + xv.z * xv.z + xv.w * xv.w;
        #pragma unroll
        for (int o = 16; o; o >>= 1) {
            s1 += __shfl_xor_sync(0xffffffffu, s1, o);
            s2 += __shfl_xor_sync(0xffffffffu, s2, o);
        }
        float mu = s1 * (1.f / 128.f);
        float var = s2 * (1.f / 128.f) - mu * mu;
        float rs = rsqrtf(var + 1e-5f);
        float4 g4 = ((const float4*)ln_g)[lane];
        float4 b4 = ((const float4*)ln_b)[lane];
        float4 o4;
        o4.x = (xv.x - mu) * rs * g4.x + b4.x;
        o4.y = (xv.y - mu) * rs * g4.y + b4.y;
        o4.z = (xv.z - mu) * rs * g4.z + b4.z;
        o4.w = (xv.w - mu) * rs * g4.w + b4.w;
        ((float4*)(g_xn + (size_t)v * D))[lane] = o4;
        ((float4*)sxn[warp])[lane] = o4;
        __syncwarp();
        float dinv = rsqrtf((float)g_deg1[v] + 1.0f);
        unsigned long long acc2 = 0ull;
        const float* sx = sxn[warp];
        #pragma unroll 16
        for (int p = 0; p < 64; p++) {
            unsigned long long xp = *(const unsigned long long*)(sx + 2 * p);
            FMA2(acc2, xp, sWp[p * 32 + lane]);
        }
        float2 u = upk(acc2);
        g_xw1[v * 32 + lane] = (u.x + u.y) * dinv;
        if (lane == 0) g_dinv1[v] = dinv;
        __syncwarp();
    }
}

// edge_features = relu(edge_attr @ ep_w + ep_b), scattered into zeroed out.
// cp.async double-buffered tile pipeline. Warp-pair split: each warp owns 64
// of the 128 output columns (2 per lane) -> half the stationary-weight
// registers, enabling 3 CTAs/SM for issue-slot coverage. red.v2 scatter.
__global__ __launch_bounds__(256, 3) void k_edgefeat(const int* __restrict__ ei,
                                                     const float* __restrict__ ea,
                                                     const float* __restrict__ ep_w,
                                                     const float* __restrict__ ep_b,
                                                     float* __restrict__ out, int e_cnt)
{
    __shared__ float s_ea[2][EF_TILE * 16];
    __shared__ int   s_dst[2][EF_TILE];

    int tid = threadIdx.x, lane = tid & 31, warp = tid >> 5;
    int pair = warp >> 1;          // 0..3, each pair handles 64 edges of the tile
    int half = warp & 1;           // which 64-column half this warp owns
    int colblk = half * 32 + lane; // float2 index within the 128-col row

    // stationary weights: 2 columns per lane, packed over k-pairs
    unsigned long long wkp[8][2];
    #pragma unroll
    for (int p = 0; p < 8; p++) {
        float2 w0 = ((const float2*)(ep_w + (size_t)(2 * p) * D))[colblk];
        float2 w1 = ((const float2*)(ep_w + (size_t)(2 * p + 1) * D))[colblk];
        wkp[p][0] = pk(w0.x, w1.x);
        wkp[p][1] = pk(w0.y, w1.y);
    }
    float2 bb = ((const float2*)ep_b)[colblk];

    uint32_t sa0 = (uint32_t)__cvta_generic_to_shared(&s_ea[0][0]);
    uint32_t sa1 = (uint32_t)__cvta_generic_to_shared(&s_ea[1][0]);
    uint32_t sd0 = (uint32_t)__cvta_generic_to_shared(&s_dst[0][0]);
    uint32_t sd1 = (uint32_t)__cvta_generic_to_shared(&s_dst[1][0]);

    int ntiles = (e_cnt + EF_TILE - 1) / EF_TILE;
    int t = blockIdx.x;
    int stride = gridDim.x;

    // stage tile t into buf 0
    if (t < ntiles) {
        int base = t * EF_TILE;
        #pragma unroll
        for (int c = tid; c < EF_TILE * 4; c += 256) {
            int eg = base + (c >> 2);
            if (eg < e_cnt) cp16(sa0 + c * 16, ea + (size_t)eg * 16 + (c & 3) * 4);
        }
        {
            int eg = base + tid;
            if (tid < EF_TILE && eg < e_cnt) cp4(sd0 + tid * 4, ei + e_cnt + eg);
        }
    }
    CP_COMMIT();

    int buf = 0;
    for (; t < ntiles; t += stride) {
        int nxt = t + stride;
        if (nxt < ntiles) {            // stage next tile into other buffer
            int base = nxt * EF_TILE;
            uint32_t sa = buf ? sa0 : sa1;
            uint32_t sd = buf ? sd0 : sd1;
            #pragma unroll
            for (int c = tid; c < EF_TILE * 4; c += 256) {
                int eg = base + (c >> 2);
                if (eg < e_cnt) cp16(sa + c * 16, ea + (size_t)eg * 16 + (c & 3) * 4);
            }
            {
                int eg = base + tid;
                if (tid < EF_TILE && eg < e_cnt) cp4(sd + tid * 4, ei + e_cnt + eg);
            }
            CP_COMMIT();
            CP_WAIT(1);                // current tile's group done
        } else {
            CP_COMMIT();
            CP_WAIT(1);
        }
        __syncthreads();

        // compute current tile: pair p handles edges [p*64, p*64+64)
        int base = t * EF_TILE;
        const float* sea = s_ea[buf];
        const int*   sds = s_dst[buf];
        int j0 = pair * 64;
        int jend = min(j0 + 64, e_cnt - base);
        for (int j = j0; j < jend; j++) {
            const ulonglong2* row = (const ulonglong2*)(sea + j * 16);
            ulonglong2 q0 = row[0], q1 = row[1];   // k pairs 0..3
            ulonglong2 q2 = row[2], q3 = row[3];   // k pairs 4..7
            int d = sds[j];
            unsigned long long t0 = 0ull, t1 = 0ull;
            FMA2(t0, q0.x, wkp[0][0]); FMA2(t1, q0.x, wkp[0][1]);
            FMA2(t0, q0.y, wkp[1][0]); FMA2(t1, q0.y, wkp[1][1]);
            FMA2(t0, q1.x, wkp[2][0]); FMA2(t1, q1.x, wkp[2][1]);
            FMA2(t0, q1.y, wkp[3][0]); FMA2(t1, q1.y, wkp[3][1]);
            FMA2(t0, q2.x, wkp[4][0]); FMA2(t1, q2.x, wkp[4][1]);
            FMA2(t0, q2.y, wkp[5][0]); FMA2(t1, q2.y, wkp[5][1]);
            FMA2(t0, q3.x, wkp[6][0]); FMA2(t1, q3.x, wkp[6][1]);
            FMA2(t0, q3.y, wkp[7][0]); FMA2(t1, q3.y, wkp[7][1]);
            float2 u0 = upk(t0), u1 = upk(t1);
            float r0 = fmaxf(bb.x + u0.x + u0.y, 0.f);
            float r1 = fmaxf(bb.y + u1.x + u1.y, 0.f);
            red2(out + (size_t)d * D + colblk * 2, r0, r1);
        }
        __syncthreads();               // buffer free before next stage cycle
        buf ^= 1;
    }
}

// scatter layer-1 messages: one thread per edge, 8 independent red4 (MLP 8).
__global__ void k_scatter1(const int* __restrict__ ei, int e_cnt) {
    int e = blockIdx.x * blockDim.x + threadIdx.x;
    if (e >= e_cnt) return;
    int s = ei[e], d = ei[e_cnt + e];
    const float4* src = (const float4*)(g_xw1 + (size_t)s * 32);
    float* dst = g_acc1 + (size_t)d * 32;
    float4 v0 = src[0], v1 = src[1], v2 = src[2], v3 = src[3];
    float4 v4 = src[4], v5 = src[5], v6 = src[6], v7 = src[7];
    red4(dst + 0,  v0); red4(dst + 4,  v1); red4(dst + 8,  v2); red4(dst + 12, v3);
    red4(dst + 16, v4); red4(dst + 20, v5); red4(dst + 24, v6); red4(dst + 28, v7);
}

// finalize h (relu) + project to layer2 logits contribution (pre-scaled by dinv1)
__global__ void k_fin1(const float* __restrict__ ia1_b, const float* __restrict__ oa1_b,
                       const float* __restrict__ ia2_w, const float* __restrict__ oa2_w, int n)
{
    int tid = blockIdx.x * blockDim.x + threadIdx.x;
    int v = tid >> 5, lane = tid & 31;
    if (v >= n) return;
    float dinv = g_dinv1[v];
    float xw1s = g_xw1[v * 32 + lane];
    float bias = (lane < 16) ? ia1_b[lane] : oa1_b[lane - 16];
    float h = dinv * g_acc1[v * 32 + lane] + xw1s * dinv + bias;
    h = fmaxf(h, 0.f);
    float w0 = (lane < 16) ? ia2_w[lane * 2] : oa2_w[(lane - 16) * 2];
    float w1 = (lane < 16) ? ia2_w[lane * 2 + 1] : oa2_w[(lane - 16) * 2 + 1];
    float p0 = h * w0, p1 = h * w1;
    #pragma unroll
    for (int o = 8; o; o >>= 1) {
        p0 += __shfl_xor_sync(0xffffffffu, p0, o);
        p1 += __shfl_xor_sync(0xffffffffu, p1, o);
    }
    if (lane == 0)  { g_t2[v * 4 + 0] = p0 * dinv; g_t2[v * 4 + 1] = p1 * dinv; }
    if (lane == 16) { g_t2[v * 4 + 2] = p0 * dinv; g_t2[v * 4 + 3] = p1 * dinv; }
}

__global__ void k_scatter2(const int* __restrict__ ei, int e_cnt) {
    int e = blockIdx.x * blockDim.x + threadIdx.x;
    if (e >= e_cnt) return;
    int s = ei[e], d = ei[e_cnt + e];
    float4 t = *(const float4*)(g_t2 + (size_t)s * 4);
    red4(g_acc2 + (size_t)d * 4, t);
}

__global__ void k_gumbel(const float* __restrict__ u_in, const float* __restrict__ u_out,
                         const float* __restrict__ ia2_b, const float* __restrict__ oa2_b, int n)
{
    int v = blockIdx.x * blockDim.x + threadIdx.x;
    if (v >= n) return;
    float dinv = g_dinv1[v];
    float li0 = dinv * g_acc2[v * 4 + 0] + g_t2[v * 4 + 0] * dinv + ia2_b[0];
    float li1 = dinv * g_acc2[v * 4 + 1] + g_t2[v * 4 + 1] * dinv + ia2_b[1];
    float lo0 = dinv * g_acc2[v * 4 + 2] + g_t2[v * 4 + 2] * dinv + oa2_b[0];
    float lo1 = dinv * g_acc2[v * 4 + 3] + g_t2[v * 4 + 3] * dinv + oa2_b[1];
    float gi0 = -logf(-logf(u_in[v * 2 + 0] + 1e-10f) + 1e-10f);
    float gi1 = -logf(-logf(u_in[v * 2 + 1] + 1e-10f) + 1e-10f);
    float go0 = -logf(-logf(u_out[v * 2 + 0] + 1e-10f) + 1e-10f);
    float go1 = -logf(-logf(u_out[v * 2 + 1] + 1e-10f) + 1e-10f);
    int in0  = (li0 + gi0 >= li1 + gi1) ? 1 : 0;
    int out0 = (lo0 + go0 >= lo1 + go1) ? 1 : 0;
    g_flags[v] = (unsigned char)(in0 | (out0 << 1));
}

// weighted degree + warp-aggregated compaction of active edges
__global__ void k_compact(const int* __restrict__ ei, int e_cnt) {
    int e = blockIdx.x * blockDim.x + threadIdx.x;
    int lane = threadIdx.x & 31;
    int s = 0, d = 0, act = 0;
    if (e < e_cnt) {
        s = ei[e]; d = ei[e_cnt + e];
        act = (g_flags[d] & 1) && ((g_flags[s] >> 1) & 1);
    }
    unsigned m = __ballot_sync(0xffffffffu, act);
    if (m) {
        int leader = __ffs(m) - 1;
        int base = 0;
        if (lane == leader) base = atomicAdd(&g_nact, __popc(m));
        base = __shfl_sync(0xffffffffu, base, leader);
        if (act) {
            int r = __popc(m & ((1u << lane) - 1));
            g_act[base + r] = make_int2(s, d);
            atomicAdd(&g_degm[d], 1);
        }
    }
}

// xw = xn @ conv_w (f32x2 packed); dinvm in epilogue; ACCUMULATES into out
// (out already holds edge-feature sums): out += xws*dinvm + conv_b.
__global__ __launch_bounds__(256) void k_gemm(const float* __restrict__ conv_w,
                                              const float* __restrict__ conv_b,
                                              float* __restrict__ out, int n)
{
    __shared__ float sA[64][32];
    __shared__ ulonglong2 sB[16 * 2 * 32];
    float* sBf = (float*)sB;
    int tid = threadIdx.x;
    int lane = tid & 31, warp = tid >> 5;
    int row0 = blockIdx.x * 64, rb = warp * 8;
    unsigned long long acc[8][4];
    #pragma unroll
    for (int r = 0; r < 8; r++)
        #pragma unroll
        for (int c = 0; c < 4; c++) acc[r][c] = 0ull;

    for (int kc = 0; kc < D; kc += 32) {
        for (int i = tid; i < 1024; i += 256) {
            int kk = i >> 5, c = i & 31;
            float4 w = ((const float4*)(conv_w + (size_t)(kc + kk) * D))[c];
            int p = kk >> 1, par = kk & 1;
            int b0i = (((p * 2 + 0) * 32 + c) << 2);
            int b1i = (((p * 2 + 1) * 32 + c) << 2);
            sBf[b0i + par]     = w.x;
            sBf[b0i + 2 + par] = w.y;
            sBf[b1i + par]     = w.z;
            sBf[b1i + 2 + par] = w.w;
        }
        for (int i = tid; i < 512; i += 256) {
            int r = i >> 3, c4 = i & 7;
            float4 vv = make_float4(0.f, 0.f, 0.f, 0.f);
            if (row0 + r < n)
                vv = ((const float4*)(g_xn + (size_t)(row0 + r) * D + kc))[c4];
            sA[r][c4 * 4 + 0] = vv.x; sA[r][c4 * 4 + 1] = vv.y;
            sA[r][c4 * 4 + 2] = vv.z; sA[r][c4 * 4 + 3] = vv.w;
        }
        __syncthreads();
        #pragma unroll
        for (int p = 0; p < 16; p++) {
            ulonglong2 b0 = sB[(p * 2 + 0) * 32 + lane];
            ulonglong2 b1 = sB[(p * 2 + 1) * 32 + lane];
            #pragma unroll
            for (int r = 0; r < 8; r++) {
                unsigned long long ap = *(const unsigned long long*)&sA[rb + r][2 * p];
                FMA2(acc[r][0], ap, b0.x);
                FMA2(acc[r][1], ap, b0.y);
                FMA2(acc[r][2], ap, b1.x);
                FMA2(acc[r][3], ap, b1.y);
            }
        }
        __syncthreads();
    }
    float4 bb = ((const float4*)conv_b)[lane];
    #pragma unroll
    for (int r = 0; r < 8; r++) {
        int v = row0 + rb + r;
        if (v < n) {
            float dm = rsqrtf((float)g_degm[v] + 1.0f);   // fused dinvm
            if (lane == 0) g_dinvm[v] = dm;
            float2 u0 = upk(acc[r][0]), u1 = upk(acc[r][1]);
            float2 u2 = upk(acc[r][2]), u3 = upk(acc[r][3]);
            float4 w = make_float4((u0.x + u0.y) * dm, (u1.x + u1.y) * dm,
                                   (u2.x + u2.y) * dm, (u3.x + u3.y) * dm);
            ((float4*)(g_xws + (size_t)v * D))[lane] = w;
            float4 prev = ((const float4*)(out + (size_t)v * D))[lane];
            float4 o = make_float4(prev.x + w.x * dm + bb.x, prev.y + w.y * dm + bb.y,
                                   prev.z + w.z * dm + bb.z, prev.w + w.w * dm + bb.w);
            ((float4*)(out + (size_t)v * D))[lane] = o;
        }
    }
}

// main conv scatter over compacted active edges; prefetched grid-stride.
__global__ void k_scatter_main(float* __restrict__ out) {
    int gw = (blockIdx.x * blockDim.x + threadIdx.x) >> 5;
    int lane = threadIdx.x & 31;
    int nw = (gridDim.x * blockDim.x) >> 5;
    int nact = g_nact;
    int e = gw;
    int2 sd_nx = make_int2(0, 0);
    if (e < nact) sd_nx = g_act[e];
    while (e < nact) {
        int2 sd = sd_nx;
        int e2 = e + nw;
        if (e2 < nact) sd_nx = g_act[e2];
        float dm = g_dinvm[sd.y];
        float4 v = ((const float4*)(g_xws + (size_t)sd.x * D))[lane];
        v.x *= dm; v.y *= dm; v.z *= dm; v.w *= dm;
        red4(out + (size_t)sd.y * D + lane * 4, v);
        e = e2;
    }
}

__global__ void k_relu(float* __restrict__ out, int n4) {
    int i = blockIdx.x * blockDim.x + threadIdx.x;
    if (i >= n4) return;
    float4 v = ((float4*)out)[i];
    v.x = fmaxf(v.x, 0.f); v.y = fmaxf(v.y, 0.f);
    v.z = fmaxf(v.z, 0.f); v.w = fmaxf(v.w, 0.f);
    ((float4*)out)[i] = v;
}

// ---------------- launch ----------------
extern "C" void kernel_launch(void* const* d_in, const int* in_sizes, int n_in,
                              void* d_out, int out_size)
{
    const float* x      = (const float*)d_in[0];
    const int*   ei     = (const int*)  d_in[1];
    const float* ea     = (const float*)d_in[2];
    const float* u_in   = (const float*)d_in[3];
    const float* u_out  = (const float*)d_in[4];
    const float* ln_g   = (const float*)d_in[5];
    const float* ln_b   = (const float*)d_in[6];
    const float* conv_w = (const float*)d_in[7];
    const float* conv_b = (const float*)d_in[8];
    const float* ep_w   = (const float*)d_in[9];
    const float* ep_b   = (const float*)d_in[10];
    const float* ia1_w  = (const float*)d_in[11];
    const float* ia1_b  = (const float*)d_in[12];
    const float* ia2_w  = (const float*)d_in[13];
    const float* ia2_b  = (const float*)d_in[14];
    const float* oa1_w  = (const float*)d_in[15];
    const float* oa1_b  = (const float*)d_in[16];
    const float* oa2_w  = (const float*)d_in[17];
    const float* oa2_b  = (const float*)d_in[18];

    int n = in_sizes[0] / D;       // 50000
    int e = in_sizes[1] / 2;       // 800000
    float* out = (float*)d_out;

    k_init<<<(n * 32 + 255) / 256, 256>>>(out, n);                     // 1
    k_deg1<<<(e + 255) / 256, 256>>>(ei, e);                           // 2
    k_ln_proj<<<592, 256>>>(x, ln_g, ln_b, ia1_w, oa1_w, n);           // 3
    k_edgefeat<<<456, 256>>>(ei, ea, ep_w, ep_b, out, e);              // 4 (profiled, 3 CTA/SM)
    k_scatter1<<<(e + 255) / 256, 256>>>(ei, e);                       // 5
    k_fin1<<<(n * 32 + 255) / 256, 256>>>(ia1_b, oa1_b, ia2_w, oa2_w, n);
    k_scatter2<<<(e + 255) / 256, 256>>>(ei, e);
    k_gumbel<<<(n + 255) / 256, 256>>>(u_in, u_out, ia2_b, oa2_b, n);
    k_compact<<<(e + 255) / 256, 256>>>(ei, e);
    k_gemm<<<(n + 63) / 64, 256>>>(conv_w, conv_b, out, n);
    k_scatter_main<<<4736, 256>>>(out);
    k_relu<<<(n * 32 + 255) / 256, 256>>>(out, n * 32);
}

// round 17
// speedup vs baseline: 1.1387x; 1.0513x over previous
#include <cuda_runtime.h>
#include <cuda_bf16.h>
#include <cstdint>

#define NMAX 50000
#define EMAX 800000
#define D 128
#define EF_TILE 256   // edges per pipeline stage in k_edgefeat

// ---------------- f32x2 packed helpers ----------------
#define FMA2(d, a, b) \
    asm("fma.rn.f32x2 %0, %1, %2, %0;" : "+l"(d) : "l"(a), "l"(b))

__device__ __forceinline__ unsigned long long pk(float lo, float hi) {
    unsigned long long r;
    asm("mov.b64 %0, {%1, %2};" : "=l"(r) : "f"(lo), "f"(hi));
    return r;
}
__device__ __forceinline__ float2 upk(unsigned long long v) {
    float lo, hi;
    asm("mov.b64 {%0, %1}, %2;" : "=f"(lo), "=f"(hi) : "l"(v));
    return make_float2(lo, hi);
}

// cp.async helpers
__device__ __forceinline__ void cp16(uint32_t saddr, const void* g) {
    asm volatile("cp.async.ca.shared.global [%0], [%1], 16;" :: "r"(saddr), "l"(g));
}
__device__ __forceinline__ void cp4(uint32_t saddr, const void* g) {
    asm volatile("cp.async.ca.shared.global [%0], [%1], 4;" :: "r"(saddr), "l"(g));
}
#define CP_COMMIT()  asm volatile("cp.async.commit_group;" ::: "memory")
#define CP_WAIT(N)   asm volatile("cp.async.wait_group %0;" :: "n"(N) : "memory")

// ---------------- device scratch ----------------
__device__ float g_xn[NMAX * D];        // layernormed x
__device__ float g_xw1[NMAX * 32];      // action layer1 projections, pre-scaled by dinv1
__device__ float g_acc1[NMAX * 32];     // scatter accumulator layer1
__device__ float g_t2[NMAX * 4];        // layer2 projections pre-scaled by dinv1
__device__ float g_acc2[NMAX * 4];      // scatter accumulator layer2
__device__ float g_dinv1[NMAX];
__device__ int   g_deg1[NMAX];
__device__ int   g_degm[NMAX];
__device__ float g_dinvm[NMAX];
__device__ unsigned char g_flags[NMAX]; // bit0 = in0, bit1 = out0
__device__ float g_xws[NMAX * D];       // (xn @ conv_w) * dinvm
__device__ int2  g_act[EMAX];           // compacted active edges (src,dst)
__device__ int   g_nact;

// vector reductions into global (sm_90+)
__device__ __forceinline__ void red4(float* p, float4 v) {
    asm volatile("red.global.add.v4.f32 [%0], {%1,%2,%3,%4};"
                 :: "l"(p), "f"(v.x), "f"(v.y), "f"(v.z), "f"(v.w) : "memory");
}
__device__ __forceinline__ void red2(float* p, float a, float b) {
    asm volatile("red.global.add.v2.f32 [%0], {%1,%2};"
                 :: "l"(p), "f"(a), "f"(b) : "memory");
}

// ---------------- kernels ----------------

// Vectorized zero of out (n*32 float4), acc1 (n*8 float4), acc2, degrees.
__global__ void k_init(float* __restrict__ out, int n) {
    int i = blockIdx.x * blockDim.x + threadIdx.x;
    float4 z = make_float4(0.f, 0.f, 0.f, 0.f);
    if (i < n * 32) ((float4*)out)[i] = z;       // out: n*128 floats
    if (i < n * 8)  ((float4*)g_acc1)[i] = z;    // acc1: n*32 floats
    if (i < n) {
        ((float4*)g_acc2)[i] = z;                // acc2: n*4 floats
        g_deg1[i] = 0;
        g_degm[i] = 0;
    }
    if (i == 0) g_nact = 0;
}

__global__ void k_deg1(const int* __restrict__ ei, int e_cnt) {
    int e = blockIdx.x * blockDim.x + threadIdx.x;
    if (e >= e_cnt) return;
    atomicAdd(&g_deg1[ei[e_cnt + e]], 1);
}

// LayerNorm + both action-net layer-1 projections (fused), f32x2 inner product.
__global__ __launch_bounds__(256) void k_ln_proj(
    const float* __restrict__ x, const float* __restrict__ ln_g, const float* __restrict__ ln_b,
    const float* __restrict__ ia1_w, const float* __restrict__ oa1_w, int n)
{
    __shared__ unsigned long long sWp[64 * 32];  // k-pairs: (W[2p][j], W[2p+1][j])
    __shared__ float sxn[8][D];
    int tid = threadIdx.x;
    for (int i = tid; i < 64 * 32; i += 256) {
        int p = i >> 5, j = i & 31;
        float w0 = (j < 16) ? ia1_w[(2 * p) * 16 + j]     : oa1_w[(2 * p) * 16 + (j - 16)];
        float w1 = (j < 16) ? ia1_w[(2 * p + 1) * 16 + j] : oa1_w[(2 * p + 1) * 16 + (j - 16)];
        sWp[i] = pk(w0, w1);
    }
    __syncthreads();
    int warp = tid >> 5, lane = tid & 31;
    int nwarps = gridDim.x * 8;
    for (int v = blockIdx.x * 8 + warp; v < n; v += nwarps) {
        float4 xv = ((const float4*)(x + (size_t)v * D))[lane];
        float s1 = xv.x + xv.y + xv.z + xv.w;
        float s2 = xv.x * xv.x + xv.y * xv.y + xv.z * xv.z + xv.w * xv.w;
        #pragma unroll
        for (int o = 16; o; o >>= 1) {
            s1 += __shfl_xor_sync(0xffffffffu, s1, o);
            s2 += __shfl_xor_sync(0xffffffffu, s2, o);
        }
        float mu = s1 * (1.f / 128.f);
        float var = s2 * (1.f / 128.f) - mu * mu;
        float rs = rsqrtf(var + 1e-5f);
        float4 g4 = ((const float4*)ln_g)[lane];
        float4 b4 = ((const float4*)ln_b)[lane];
        float4 o4;
        o4.x = (xv.x - mu) * rs * g4.x + b4.x;
        o4.y = (xv.y - mu) * rs * g4.y + b4.y;
        o4.z = (xv.z - mu) * rs * g4.z + b4.z;
        o4.w = (xv.w - mu) * rs * g4.w + b4.w;
        ((float4*)(g_xn + (size_t)v * D))[lane] = o4;
        ((float4*)sxn[warp])[lane] = o4;
        __syncwarp();
        float dinv = rsqrtf((float)g_deg1[v] + 1.0f);
        unsigned long long acc2 = 0ull;
        const float* sx = sxn[warp];
        #pragma unroll 16
        for (int p = 0; p < 64; p++) {
            unsigned long long xp = *(const unsigned long long*)(sx + 2 * p);
            FMA2(acc2, xp, sWp[p * 32 + lane]);
        }
        float2 u = upk(acc2);
        g_xw1[v * 32 + lane] = (u.x + u.y) * dinv;
        if (lane == 0) g_dinv1[v] = dinv;
        __syncwarp();
    }
}

// edge_features = relu(edge_attr @ ep_w + ep_b), scattered into zeroed out.
// cp.async double-buffered tile pipeline, warp-pair column split (80 regs).
// Grid 304 = 2 CTA/SM, leaving regfile/smem headroom so the concurrent
// atomic-chain kernels on the other stream can co-schedule.
__global__ __launch_bounds__(256, 3) void k_edgefeat(const int* __restrict__ ei,
                                                     const float* __restrict__ ea,
                                                     const float* __restrict__ ep_w,
                                                     const float* __restrict__ ep_b,
                                                     float* __restrict__ out, int e_cnt)
{
    __shared__ float s_ea[2][EF_TILE * 16];
    __shared__ int   s_dst[2][EF_TILE];

    int tid = threadIdx.x, lane = tid & 31, warp = tid >> 5;
    int pair = warp >> 1;          // 0..3, each pair handles 64 edges of the tile
    int half = warp & 1;           // which 64-column half this warp owns
    int colblk = half * 32 + lane; // float2 index within the 128-col row

    unsigned long long wkp[8][2];
    #pragma unroll
    for (int p = 0; p < 8; p++) {
        float2 w0 = ((const float2*)(ep_w + (size_t)(2 * p) * D))[colblk];
        float2 w1 = ((const float2*)(ep_w + (size_t)(2 * p + 1) * D))[colblk];
        wkp[p][0] = pk(w0.x, w1.x);
        wkp[p][1] = pk(w0.y, w1.y);
    }
    float2 bb = ((const float2*)ep_b)[colblk];

    uint32_t sa0 = (uint32_t)__cvta_generic_to_shared(&s_ea[0][0]);
    uint32_t sa1 = (uint32_t)__cvta_generic_to_shared(&s_ea[1][0]);
    uint32_t sd0 = (uint32_t)__cvta_generic_to_shared(&s_dst[0][0]);
    uint32_t sd1 = (uint32_t)__cvta_generic_to_shared(&s_dst[1][0]);

    int ntiles = (e_cnt + EF_TILE - 1) / EF_TILE;
    int t = blockIdx.x;
    int stride = gridDim.x;

    if (t < ntiles) {
        int base = t * EF_TILE;
        #pragma unroll
        for (int c = tid; c < EF_TILE * 4; c += 256) {
            int eg = base + (c >> 2);
            if (eg < e_cnt) cp16(sa0 + c * 16, ea + (size_t)eg * 16 + (c & 3) * 4);
        }
        {
            int eg = base + tid;
            if (tid < EF_TILE && eg < e_cnt) cp4(sd0 + tid * 4, ei + e_cnt + eg);
        }
    }
    CP_COMMIT();

    int buf = 0;
    for (; t < ntiles; t += stride) {
        int nxt = t + stride;
        if (nxt < ntiles) {
            int base = nxt * EF_TILE;
            uint32_t sa = buf ? sa0 : sa1;
            uint32_t sd = buf ? sd0 : sd1;
            #pragma unroll
            for (int c = tid; c < EF_TILE * 4; c += 256) {
                int eg = base + (c >> 2);
                if (eg < e_cnt) cp16(sa + c * 16, ea + (size_t)eg * 16 + (c & 3) * 4);
            }
            {
                int eg = base + tid;
                if (tid < EF_TILE && eg < e_cnt) cp4(sd + tid * 4, ei + e_cnt + eg);
            }
            CP_COMMIT();
            CP_WAIT(1);
        } else {
            CP_COMMIT();
            CP_WAIT(1);
        }
        __syncthreads();

        int base = t * EF_TILE;
        const float* sea = s_ea[buf];
        const int*   sds = s_dst[buf];
        int j0 = pair * 64;
        int jend = min(j0 + 64, e_cnt - base);
        for (int j = j0; j < jend; j++) {
            const ulonglong2* row = (const ulonglong2*)(sea + j * 16);
            ulonglong2 q0 = row[0], q1 = row[1];
            ulonglong2 q2 = row[2], q3 = row[3];
            int d = sds[j];
            unsigned long long t0 = 0ull, t1 = 0ull;
            FMA2(t0, q0.x, wkp[0][0]); FMA2(t1, q0.x, wkp[0][1]);
            FMA2(t0, q0.y, wkp[1][0]); FMA2(t1, q0.y, wkp[1][1]);
            FMA2(t0, q1.x, wkp[2][0]); FMA2(t1, q1.x, wkp[2][1]);
            FMA2(t0, q1.y, wkp[3][0]); FMA2(t1, q1.y, wkp[3][1]);
            FMA2(t0, q2.x, wkp[4][0]); FMA2(t1, q2.x, wkp[4][1]);
            FMA2(t0, q2.y, wkp[5][0]); FMA2(t1, q2.y, wkp[5][1]);
            FMA2(t0, q3.x, wkp[6][0]); FMA2(t1, q3.x, wkp[6][1]);
            FMA2(t0, q3.y, wkp[7][0]); FMA2(t1, q3.y, wkp[7][1]);
            float2 u0 = upk(t0), u1 = upk(t1);
            float r0 = fmaxf(bb.x + u0.x + u0.y, 0.f);
            float r1 = fmaxf(bb.y + u1.x + u1.y, 0.f);
            red2(out + (size_t)d * D + colblk * 2, r0, r1);
        }
        __syncthreads();
        buf ^= 1;
    }
}

// scatter layer-1 messages: one thread per edge, 8 independent red4 (MLP 8).
__global__ void k_scatter1(const int* __restrict__ ei, int e_cnt) {
    int e = blockIdx.x * blockDim.x + threadIdx.x;
    if (e >= e_cnt) return;
    int s = ei[e], d = ei[e_cnt + e];
    const float4* src = (const float4*)(g_xw1 + (size_t)s * 32);
    float* dst = g_acc1 + (size_t)d * 32;
    float4 v0 = src[0], v1 = src[1], v2 = src[2], v3 = src[3];
    float4 v4 = src[4], v5 = src[5], v6 = src[6], v7 = src[7];
    red4(dst + 0,  v0); red4(dst + 4,  v1); red4(dst + 8,  v2); red4(dst + 12, v3);
    red4(dst + 16, v4); red4(dst + 20, v5); red4(dst + 24, v6); red4(dst + 28, v7);
}

// finalize h (relu) + project to layer2 logits contribution (pre-scaled by dinv1)
__global__ void k_fin1(const float* __restrict__ ia1_b, const float* __restrict__ oa1_b,
                       const float* __restrict__ ia2_w, const float* __restrict__ oa2_w, int n)
{
    int tid = blockIdx.x * blockDim.x + threadIdx.x;
    int v = tid >> 5, lane = tid & 31;
    if (v >= n) return;
    float dinv = g_dinv1[v];
    float xw1s = g_xw1[v * 32 + lane];
    float bias = (lane < 16) ? ia1_b[lane] : oa1_b[lane - 16];
    float h = dinv * g_acc1[v * 32 + lane] + xw1s * dinv + bias;
    h = fmaxf(h, 0.f);
    float w0 = (lane < 16) ? ia2_w[lane * 2] : oa2_w[(lane - 16) * 2];
    float w1 = (lane < 16) ? ia2_w[lane * 2 + 1] : oa2_w[(lane - 16) * 2 + 1];
    float p0 = h * w0, p1 = h * w1;
    #pragma unroll
    for (int o = 8; o; o >>= 1) {
        p0 += __shfl_xor_sync(0xffffffffu, p0, o);
        p1 += __shfl_xor_sync(0xffffffffu, p1, o);
    }
    if (lane == 0)  { g_t2[v * 4 + 0] = p0 * dinv; g_t2[v * 4 + 1] = p1 * dinv; }
    if (lane == 16) { g_t2[v * 4 + 2] = p0 * dinv; g_t2[v * 4 + 3] = p1 * dinv; }
}

__global__ void k_scatter2(const int* __restrict__ ei, int e_cnt) {
    int e = blockIdx.x * blockDim.x + threadIdx.x;
    if (e >= e_cnt) return;
    int s = ei[e], d = ei[e_cnt + e];
    float4 t = *(const float4*)(g_t2 + (size_t)s * 4);
    red4(g_acc2 + (size_t)d * 4, t);
}

__global__ void k_gumbel(const float* __restrict__ u_in, const float* __restrict__ u_out,
                         const float* __restrict__ ia2_b, const float* __restrict__ oa2_b, int n)
{
    int v = blockIdx.x * blockDim.x + threadIdx.x;
    if (v >= n) return;
    float dinv = g_dinv1[v];
    float li0 = dinv * g_acc2[v * 4 + 0] + g_t2[v * 4 + 0] * dinv + ia2_b[0];
    float li1 = dinv * g_acc2[v * 4 + 1] + g_t2[v * 4 + 1] * dinv + ia2_b[1];
    float lo0 = dinv * g_acc2[v * 4 + 2] + g_t2[v * 4 + 2] * dinv + oa2_b[0];
    float lo1 = dinv * g_acc2[v * 4 + 3] + g_t2[v * 4 + 3] * dinv + oa2_b[1];
    float gi0 = -logf(-logf(u_in[v * 2 + 0] + 1e-10f) + 1e-10f);
    float gi1 = -logf(-logf(u_in[v * 2 + 1] + 1e-10f) + 1e-10f);
    float go0 = -logf(-logf(u_out[v * 2 + 0] + 1e-10f) + 1e-10f);
    float go1 = -logf(-logf(u_out[v * 2 + 1] + 1e-10f) + 1e-10f);
    int in0  = (li0 + gi0 >= li1 + gi1) ? 1 : 0;
    int out0 = (lo0 + go0 >= lo1 + go1) ? 1 : 0;
    g_flags[v] = (unsigned char)(in0 | (out0 << 1));
}

// weighted degree + warp-aggregated compaction of active edges
__global__ void k_compact(const int* __restrict__ ei, int e_cnt) {
    int e = blockIdx.x * blockDim.x + threadIdx.x;
    int lane = threadIdx.x & 31;
    int s = 0, d = 0, act = 0;
    if (e < e_cnt) {
        s = ei[e]; d = ei[e_cnt + e];
        act = (g_flags[d] & 1) && ((g_flags[s] >> 1) & 1);
    }
    unsigned m = __ballot_sync(0xffffffffu, act);
    if (m) {
        int leader = __ffs(m) - 1;
        int base = 0;
        if (lane == leader) base = atomicAdd(&g_nact, __popc(m));
        base = __shfl_sync(0xffffffffu, base, leader);
        if (act) {
            int r = __popc(m & ((1u << lane) - 1));
            g_act[base + r] = make_int2(s, d);
            atomicAdd(&g_degm[d], 1);
        }
    }
}

// xw = xn @ conv_w (f32x2 packed); dinvm in epilogue; ACCUMULATES into out
// (out already holds edge-feature sums): out += xws*dinvm + conv_b.
__global__ __launch_bounds__(256) void k_gemm(const float* __restrict__ conv_w,
                                              const float* __restrict__ conv_b,
                                              float* __restrict__ out, int n)
{
    __shared__ float sA[64][32];
    __shared__ ulonglong2 sB[16 * 2 * 32];
    float* sBf = (float*)sB;
    int tid = threadIdx.x;
    int lane = tid & 31, warp = tid >> 5;
    int row0 = blockIdx.x * 64, rb = warp * 8;
    unsigned long long acc[8][4];
    #pragma unroll
    for (int r = 0; r < 8; r++)
        #pragma unroll
        for (int c = 0; c < 4; c++) acc[r][c] = 0ull;

    for (int kc = 0; kc < D; kc += 32) {
        for (int i = tid; i < 1024; i += 256) {
            int kk = i >> 5, c = i & 31;
            float4 w = ((const float4*)(conv_w + (size_t)(kc + kk) * D))[c];
            int p = kk >> 1, par = kk & 1;
            int b0i = (((p * 2 + 0) * 32 + c) << 2);
            int b1i = (((p * 2 + 1) * 32 + c) << 2);
            sBf[b0i + par]     = w.x;
            sBf[b0i + 2 + par] = w.y;
            sBf[b1i + par]     = w.z;
            sBf[b1i + 2 + par] = w.w;
        }
        for (int i = tid; i < 512; i += 256) {
            int r = i >> 3, c4 = i & 7;
            float4 vv = make_float4(0.f, 0.f, 0.f, 0.f);
            if (row0 + r < n)
                vv = ((const float4*)(g_xn + (size_t)(row0 + r) * D + kc))[c4];
            sA[r][c4 * 4 + 0] = vv.x; sA[r][c4 * 4 + 1] = vv.y;
            sA[r][c4 * 4 + 2] = vv.z; sA[r][c4 * 4 + 3] = vv.w;
        }
        __syncthreads();
        #pragma unroll
        for (int p = 0; p < 16; p++) {
            ulonglong2 b0 = sB[(p * 2 + 0) * 32 + lane];
            ulonglong2 b1 = sB[(p * 2 + 1) * 32 + lane];
            #pragma unroll
            for (int r = 0; r < 8; r++) {
                unsigned long long ap = *(const unsigned long long*)&sA[rb + r][2 * p];
                FMA2(acc[r][0], ap, b0.x);
                FMA2(acc[r][1], ap, b0.y);
                FMA2(acc[r][2], ap, b1.x);
                FMA2(acc[r][3], ap, b1.y);
            }
        }
        __syncthreads();
    }
    float4 bb = ((const float4*)conv_b)[lane];
    #pragma unroll
    for (int r = 0; r < 8; r++) {
        int v = row0 + rb + r;
        if (v < n) {
            float dm = rsqrtf((float)g_degm[v] + 1.0f);   // fused dinvm
            if (lane == 0) g_dinvm[v] = dm;
            float2 u0 = upk(acc[r][0]), u1 = upk(acc[r][1]);
            float2 u2 = upk(acc[r][2]), u3 = upk(acc[r][3]);
            float4 w = make_float4((u0.x + u0.y) * dm, (u1.x + u1.y) * dm,
                                   (u2.x + u2.y) * dm, (u3.x + u3.y) * dm);
            ((float4*)(g_xws + (size_t)v * D))[lane] = w;
            float4 prev = ((const float4*)(out + (size_t)v * D))[lane];
            float4 o = make_float4(prev.x + w.x * dm + bb.x, prev.y + w.y * dm + bb.y,
                                   prev.z + w.z * dm + bb.z, prev.w + w.w * dm + bb.w);
            ((float4*)(out + (size_t)v * D))[lane] = o;
        }
    }
}

// main conv scatter over compacted active edges; prefetched grid-stride.
__global__ void k_scatter_main(float* __restrict__ out) {
    int gw = (blockIdx.x * blockDim.x + threadIdx.x) >> 5;
    int lane = threadIdx.x & 31;
    int nw = (gridDim.x * blockDim.x) >> 5;
    int nact = g_nact;
    int e = gw;
    int2 sd_nx = make_int2(0, 0);
    if (e < nact) sd_nx = g_act[e];
    while (e < nact) {
        int2 sd = sd_nx;
        int e2 = e + nw;
        if (e2 < nact) sd_nx = g_act[e2];
        float dm = g_dinvm[sd.y];
        float4 v = ((const float4*)(g_xws + (size_t)sd.x * D))[lane];
        v.x *= dm; v.y *= dm; v.z *= dm; v.w *= dm;
        red4(out + (size_t)sd.y * D + lane * 4, v);
        e = e2;
    }
}

__global__ void k_relu(float* __restrict__ out, int n4) {
    int i = blockIdx.x * blockDim.x + threadIdx.x;
    if (i >= n4) return;
    float4 v = ((float4*)out)[i];
    v.x = fmaxf(v.x, 0.f); v.y = fmaxf(v.y, 0.f);
    v.z = fmaxf(v.z, 0.f); v.w = fmaxf(v.w, 0.f);
    ((float4*)out)[i] = v;
}

// ---------------- launch ----------------
extern "C" void kernel_launch(void* const* d_in, const int* in_sizes, int n_in,
                              void* d_out, int out_size)
{
    const float* x      = (const float*)d_in[0];
    const int*   ei     = (const int*)  d_in[1];
    const float* ea     = (const float*)d_in[2];
    const float* u_in   = (const float*)d_in[3];
    const float* u_out  = (const float*)d_in[4];
    const float* ln_g   = (const float*)d_in[5];
    const float* ln_b   = (const float*)d_in[6];
    const float* conv_w = (const float*)d_in[7];
    const float* conv_b = (const float*)d_in[8];
    const float* ep_w   = (const float*)d_in[9];
    const float* ep_b   = (const float*)d_in[10];
    const float* ia1_w  = (const float*)d_in[11];
    const float* ia1_b  = (const float*)d_in[12];
    const float* ia2_w  = (const float*)d_in[13];
    const float* ia2_b  = (const float*)d_in[14];
    const float* oa1_w  = (const float*)d_in[15];
    const float* oa1_b  = (const float*)d_in[16];
    const float* oa2_w  = (const float*)d_in[17];
    const float* oa2_b  = (const float*)d_in[18];

    int n = in_sizes[0] / D;       // 50000
    int e = in_sizes[1] / 2;       // 800000
    float* out = (float*)d_out;

    // Lazy one-time stream/event creation (validated fork pattern from R15;
    // capture absorbs it as parallel graph branches).
    static cudaStream_t s2 = nullptr;
    static cudaEvent_t evFork = nullptr, evJoin = nullptr;
    if (s2 == nullptr) {
        cudaStreamCreateWithFlags(&s2, cudaStreamNonBlocking);
        cudaEventCreateWithFlags(&evFork, cudaEventDisableTiming);
        cudaEventCreateWithFlags(&evJoin, cudaEventDisableTiming);
    }

    // serial prefix: init, deg1, ln_proj (ln_proj must NOT co-run — R15 lesson)
    k_init<<<(n * 32 + 255) / 256, 256>>>(out, n);
    k_deg1<<<(e + 255) / 256, 256>>>(ei, e);
    k_ln_proj<<<592, 256>>>(x, ln_g, ln_b, ia1_w, oa1_w, n);

    // fork: edgefeat (issue-bound, 2 CTA/SM with headroom) overlaps the
    // atomic-latency chain (issue 2-20% => idle slots for edgefeat).
    cudaEventRecord(evFork, 0);
    cudaStreamWaitEvent(s2, evFork, 0);
    k_edgefeat<<<304, 256, 0, s2>>>(ei, ea, ep_w, ep_b, out, e);
    cudaEventRecord(evJoin, s2);

    k_scatter1<<<(e + 255) / 256, 256>>>(ei, e);
    k_fin1<<<(n * 32 + 255) / 256, 256>>>(ia1_b, oa1_b, ia2_w, oa2_w, n);
    k_scatter2<<<(e + 255) / 256, 256>>>(ei, e);
    k_gumbel<<<(n + 255) / 256, 256>>>(u_in, u_out, ia2_b, oa2_b, n);
    k_compact<<<(e + 255) / 256, 256>>>(ei, e);

    // join: gemm needs out (edgefeat), xn (ln_proj), degm (compact)
    cudaStreamWaitEvent(0, evJoin, 0);
    k_gemm<<<(n + 63) / 64, 256>>>(conv_w, conv_b, out, n);
    k_scatter_main<<<4736, 256>>>(out);
    k_relu<<<(n * 32 + 255) / 256, 256>>>(out, n * 32);
}